// round 1
// baseline (speedup 1.0000x reference)
#include <cuda_runtime.h>
#include <math.h>

// Problem constants
#define BB   2
#define TT   2048
#define DD   1024
#define HH   16
#define DHD  64
#define FFD  4096
#define ROWS (BB*TT)          // 4096 token rows

// ---------------- scratch (no allocations allowed) ----------------
__device__ float g_h  [ROWS*DD];   // LN output (reused for LN2)
__device__ float g_q  [ROWS*DD];
__device__ float g_k  [ROWS*DD];
__device__ float g_v  [ROWS*DD];
__device__ float g_att[ROWS*DD];   // attention output, (B,T,H,DH)=(B,T,D)
__device__ float g_ff [ROWS*FFD];  // FFN hidden

// ---------------- LayerNorm: one block per row ----------------
__global__ void ln_kernel(const float* __restrict__ x, const float* __restrict__ g,
                          const float* __restrict__ b, float* __restrict__ y) {
    __shared__ float red[2][8];
    const int row = blockIdx.x;
    const float* xr = x + (size_t)row * DD;
    float vloc[4];
    float s = 0.f, s2 = 0.f;
#pragma unroll
    for (int i = 0; i < 4; i++) {
        float t = xr[threadIdx.x + 256 * i];
        vloc[i] = t; s += t; s2 += t * t;
    }
#pragma unroll
    for (int o = 16; o; o >>= 1) {
        s  += __shfl_xor_sync(0xffffffffu, s,  o);
        s2 += __shfl_xor_sync(0xffffffffu, s2, o);
    }
    const int w = threadIdx.x >> 5, lane = threadIdx.x & 31;
    if (!lane) { red[0][w] = s; red[1][w] = s2; }
    __syncthreads();
    if (threadIdx.x < 32) {
        s  = (lane < 8) ? red[0][lane] : 0.f;
        s2 = (lane < 8) ? red[1][lane] : 0.f;
#pragma unroll
        for (int o = 4; o; o >>= 1) {
            s  += __shfl_xor_sync(0xffffffffu, s,  o);
            s2 += __shfl_xor_sync(0xffffffffu, s2, o);
        }
        if (!lane) { red[0][0] = s; red[1][0] = s2; }
    }
    __syncthreads();
    s = red[0][0]; s2 = red[1][0];
    const float mu  = s * (1.f / DD);
    const float var = s2 * (1.f / DD) - mu * mu;
    const float inv = rsqrtf(var + 1e-5f);
    float* yr = y + (size_t)row * DD;
#pragma unroll
    for (int i = 0; i < 4; i++) {
        int c = threadIdx.x + 256 * i;
        yr[c] = (vloc[i] - mu) * inv * g[c] + b[c];
    }
}

// ---------------- C[M,N] = A[M,K] * W[N,K]^T (+epilogue) ----------------
// 64x64 block tile, BK=16, 256 threads, 4x4 per thread.
// EPI: 0 = none, 1 = add residual R, 2 = exact GELU
template <int EPI>
__global__ void gemm_nt(const float* __restrict__ A, const float* __restrict__ W,
                        const float* __restrict__ R, float* __restrict__ C,
                        int M, int N, int K) {
    __shared__ float As[16][65];
    __shared__ float Bs[16][65];
    const int tid = threadIdx.x;
    const int tx = tid & 15, ty = tid >> 4;
    const int m0 = blockIdx.y * 64, n0 = blockIdx.x * 64;
    const int lrow = tid >> 2;   // 0..63
    const int lq   = tid & 3;    // float4 slot within 16-wide k tile

    float acc[4][4] = {};
    const float* Ap = A + (size_t)(m0 + lrow) * K + lq * 4;
    const float* Wp = W + (size_t)(n0 + lrow) * K + lq * 4;

    for (int k0 = 0; k0 < K; k0 += 16) {
        float4 av = *(const float4*)(Ap + k0);
        float4 wv = *(const float4*)(Wp + k0);
        As[lq * 4 + 0][lrow] = av.x; As[lq * 4 + 1][lrow] = av.y;
        As[lq * 4 + 2][lrow] = av.z; As[lq * 4 + 3][lrow] = av.w;
        Bs[lq * 4 + 0][lrow] = wv.x; Bs[lq * 4 + 1][lrow] = wv.y;
        Bs[lq * 4 + 2][lrow] = wv.z; Bs[lq * 4 + 3][lrow] = wv.w;
        __syncthreads();
#pragma unroll
        for (int kk = 0; kk < 16; kk++) {
            float a[4], b[4];
#pragma unroll
            for (int i = 0; i < 4; i++) a[i] = As[kk][ty * 4 + i];
#pragma unroll
            for (int j = 0; j < 4; j++) b[j] = Bs[kk][tx * 4 + j];
#pragma unroll
            for (int i = 0; i < 4; i++)
#pragma unroll
                for (int j = 0; j < 4; j++) acc[i][j] += a[i] * b[j];
        }
        __syncthreads();
    }

#pragma unroll
    for (int i = 0; i < 4; i++) {
#pragma unroll
        for (int j = 0; j < 4; j++) {
            const int row = m0 + ty * 4 + i;
            const int col = n0 + tx * 4 + j;
            float v = acc[i][j];
            if (EPI == 1) v += R[(size_t)row * N + col];
            if (EPI == 2) v = 0.5f * v * (1.f + erff(v * 0.70710678118654752f));
            C[(size_t)row * N + col] = v;
        }
    }
}

// ---------------- Causal flash attention (fp32), DH=64 ----------------
// grid: (T/64, H, B), 256 threads. 64x64 Q tile; streaming softmax over K tiles.
// Thread (ty,tx) owns a 4x4 microtile of S / O (rows ty*4+i, cols tx*4+j).
__global__ void attn_kernel(const float* __restrict__ Q, const float* __restrict__ K,
                            const float* __restrict__ V, float* __restrict__ O) {
    extern __shared__ float sm[];
    float* Qs = sm;                 // [64][65]
    float* Ks = sm + 4160;
    float* Vs = sm + 8320;
    float* Ps = sm + 12480;

    const int tid = threadIdx.x;
    const int tx = tid & 15, ty = tid >> 4;
    const int q0 = blockIdx.x * 64;
    const int h  = blockIdx.y;
    const int b  = blockIdx.z;
    const size_t base = ((size_t)b * TT * HH + h) * DHD;   // + t*(HH*DHD) + d
    const int RS = HH * DHD;  // 1024: row stride in (B,T,H,DH)

    // load Q tile
    for (int i = tid; i < 1024; i += 256) {
        int row = i >> 4, c4 = i & 15;
        float4 qv = *(const float4*)(Q + base + (size_t)(q0 + row) * RS + c4 * 4);
        float* d = &Qs[row * 65 + c4 * 4];
        d[0] = qv.x; d[1] = qv.y; d[2] = qv.z; d[3] = qv.w;
    }

    float acc[4][4] = {};
    float m[4], l[4];
#pragma unroll
    for (int i = 0; i < 4; i++) { m[i] = -1e30f; l[i] = 0.f; }
    __syncthreads();

    for (int k0 = 0; k0 <= q0; k0 += 64) {
        for (int i = tid; i < 1024; i += 256) {
            int row = i >> 4, c4 = i & 15;
            float4 kv = *(const float4*)(K + base + (size_t)(k0 + row) * RS + c4 * 4);
            float4 vv = *(const float4*)(V + base + (size_t)(k0 + row) * RS + c4 * 4);
            float* kd = &Ks[row * 65 + c4 * 4];
            kd[0] = kv.x; kd[1] = kv.y; kd[2] = kv.z; kd[3] = kv.w;
            float* vd = &Vs[row * 65 + c4 * 4];
            vd[0] = vv.x; vd[1] = vv.y; vd[2] = vv.z; vd[3] = vv.w;
        }
        __syncthreads();

        // S = Q K^T (4x4 per thread)
        float s[4][4] = {};
#pragma unroll 8
        for (int d = 0; d < 64; d++) {
            float a[4], bb[4];
#pragma unroll
            for (int i = 0; i < 4; i++) a[i]  = Qs[(ty * 4 + i) * 65 + d];
#pragma unroll
            for (int j = 0; j < 4; j++) bb[j] = Ks[(tx * 4 + j) * 65 + d];
#pragma unroll
            for (int i = 0; i < 4; i++)
#pragma unroll
                for (int j = 0; j < 4; j++) s[i][j] += a[i] * bb[j];
        }

        const bool lastt = (k0 == q0);
#pragma unroll
        for (int i = 0; i < 4; i++)
#pragma unroll
            for (int j = 0; j < 4; j++) {
                s[i][j] *= 0.125f;  // 1/sqrt(64)
                if (lastt && (tx * 4 + j > ty * 4 + i)) s[i][j] = -1e30f;
            }

        // streaming softmax per row (16 tx-lanes share a row: half-warp shfl reduce)
#pragma unroll
        for (int i = 0; i < 4; i++) {
            float mloc = fmaxf(fmaxf(s[i][0], s[i][1]), fmaxf(s[i][2], s[i][3]));
#pragma unroll
            for (int o = 8; o >= 1; o >>= 1)
                mloc = fmaxf(mloc, __shfl_xor_sync(0xffffffffu, mloc, o));
            const float mnew = fmaxf(m[i], mloc);
            const float f = __expf(m[i] - mnew);
            float ls = 0.f;
#pragma unroll
            for (int j = 0; j < 4; j++) { s[i][j] = __expf(s[i][j] - mnew); ls += s[i][j]; }
#pragma unroll
            for (int o = 8; o >= 1; o >>= 1)
                ls += __shfl_xor_sync(0xffffffffu, ls, o);
            l[i] = l[i] * f + ls;
            m[i] = mnew;
#pragma unroll
            for (int j = 0; j < 4; j++) acc[i][j] *= f;
#pragma unroll
            for (int j = 0; j < 4; j++) Ps[(ty * 4 + i) * 65 + tx * 4 + j] = s[i][j];
        }
        __syncwarp();

        // O += P V
#pragma unroll 8
        for (int j = 0; j < 64; j++) {
            float p[4], vv[4];
#pragma unroll
            for (int i = 0; i < 4; i++) p[i] = Ps[(ty * 4 + i) * 65 + j];
#pragma unroll
            for (int c = 0; c < 4; c++) vv[c] = Vs[j * 65 + tx * 4 + c];
#pragma unroll
            for (int i = 0; i < 4; i++)
#pragma unroll
                for (int c = 0; c < 4; c++) acc[i][c] += p[i] * vv[c];
        }
        __syncthreads();
    }

#pragma unroll
    for (int i = 0; i < 4; i++) {
        const float linv = 1.f / l[i];
#pragma unroll
        for (int j = 0; j < 4; j++) {
            const int row = ty * 4 + i, col = tx * 4 + j;
            O[base + (size_t)(q0 + row) * RS + col] = acc[i][j] * linv;
        }
    }
}

// ---------------- host entry ----------------
extern "C" void kernel_launch(void* const* d_in, const int* in_sizes, int n_in,
                              void* d_out, int out_size) {
    const float* x     = (const float*)d_in[0];
    // d_in[1] = mask (causal; implemented analytically, unused)
    const float* ln1_g = (const float*)d_in[2];
    const float* ln1_b = (const float*)d_in[3];
    const float* ln2_g = (const float*)d_in[4];
    const float* ln2_b = (const float*)d_in[5];
    const float* Wq    = (const float*)d_in[6];
    const float* Wk    = (const float*)d_in[7];
    const float* Wv    = (const float*)d_in[8];
    const float* Wo    = (const float*)d_in[9];
    const float* Wff1  = (const float*)d_in[10];
    const float* Wff2  = (const float*)d_in[11];
    float* out = (float*)d_out;

    float *h, *q, *k, *v, *att, *ff;
    cudaGetSymbolAddress((void**)&h,   g_h);
    cudaGetSymbolAddress((void**)&q,   g_q);
    cudaGetSymbolAddress((void**)&k,   g_k);
    cudaGetSymbolAddress((void**)&v,   g_v);
    cudaGetSymbolAddress((void**)&att, g_att);
    cudaGetSymbolAddress((void**)&ff,  g_ff);

    const int SMEM_ATTN = 4 * 4160 * 4;  // 66560 B
    cudaFuncSetAttribute(attn_kernel, cudaFuncAttributeMaxDynamicSharedMemorySize, SMEM_ATTN);

    // h = LN1(x)
    ln_kernel<<<ROWS, 256>>>(x, ln1_g, ln1_b, h);

    // Q,K,V projections
    dim3 gP(DD / 64, ROWS / 64);
    gemm_nt<0><<<gP, 256>>>(h, Wq, nullptr, q, ROWS, DD, DD);
    gemm_nt<0><<<gP, 256>>>(h, Wk, nullptr, k, ROWS, DD, DD);
    gemm_nt<0><<<gP, 256>>>(h, Wv, nullptr, v, ROWS, DD, DD);

    // causal attention
    attn_kernel<<<dim3(TT / 64, HH, BB), 256, SMEM_ATTN>>>(q, k, v, att);

    // x2 = x + att @ Wo^T   -> out
    gemm_nt<1><<<gP, 256>>>(att, Wo, x, out, ROWS, DD, DD);

    // h = LN2(x2)
    ln_kernel<<<ROWS, 256>>>(out, ln2_g, ln2_b, h);

    // ff = gelu(h @ Wff1^T)
    gemm_nt<2><<<dim3(FFD / 64, ROWS / 64), 256>>>(h, Wff1, nullptr, ff, ROWS, FFD, DD);

    // out = x2 + ff @ Wff2^T
    gemm_nt<1><<<gP, 256>>>(ff, Wff2, out, out, ROWS, DD, FFD);
}

// round 4
// speedup vs baseline: 3.0749x; 3.0749x over previous
#include <cuda_runtime.h>
#include <cuda_fp16.h>
#include <math.h>
#include <stdint.h>

// Problem constants
#define BB   2
#define TT   2048
#define DD   1024
#define HH   16
#define DHD  64
#define FFD  4096
#define ROWS (BB*TT)          // 4096 token rows

// ---------------- scratch (no allocations allowed) ----------------
__device__ __half g_hhi [ROWS*DD],  g_hlo [ROWS*DD];   // LN out split
__device__ float  g_q   [ROWS*DD];
__device__ float  g_k   [ROWS*DD];
__device__ float  g_v   [ROWS*DD];
__device__ __half g_atthi[ROWS*DD], g_attlo[ROWS*DD];  // attention out split
__device__ __half g_ffhi [ROWS*FFD], g_fflo [ROWS*FFD]; // FFN hidden split
__device__ __half g_wq16[DD*DD], g_wk16[DD*DD], g_wv16[DD*DD], g_wo16[DD*DD];
__device__ __half g_wf1_16[FFD*DD], g_wf2_16[DD*FFD];

// ================= low-level helpers (base ISA only) ===========
__device__ __forceinline__ uint32_t smem_u32(const void* p) {
    uint32_t a;
    asm("{ .reg .u64 t; cvta.to.shared.u64 t, %1; cvt.u32.u64 %0, t; }" : "=r"(a) : "l"(p));
    return a;
}
__device__ __forceinline__ void cp16(uint32_t s, const void* g) {
    asm volatile("cp.async.cg.shared.global [%0], [%1], 16;\n" :: "r"(s), "l"(g));
}
#define CP_COMMIT() asm volatile("cp.async.commit_group;\n" ::: "memory")
#define CP_WAIT(n)  asm volatile("cp.async.wait_group %0;\n" :: "n"(n) : "memory")

__device__ __forceinline__ void ldsm4(uint32_t& r0, uint32_t& r1, uint32_t& r2, uint32_t& r3,
                                      uint32_t addr) {
    asm volatile("ldmatrix.sync.aligned.m8n8.x4.shared.b16 {%0,%1,%2,%3}, [%4];"
                 : "=r"(r0), "=r"(r1), "=r"(r2), "=r"(r3) : "r"(addr));
}
__device__ __forceinline__ void mma16816(float* d, const uint32_t* a, const uint32_t* b) {
    asm volatile("mma.sync.aligned.m16n8k16.row.col.f32.f16.f16.f32 "
                 "{%0,%1,%2,%3}, {%4,%5,%6,%7}, {%8,%9}, {%0,%1,%2,%3};"
                 : "+f"(d[0]), "+f"(d[1]), "+f"(d[2]), "+f"(d[3])
                 : "r"(a[0]), "r"(a[1]), "r"(a[2]), "r"(a[3]), "r"(b[0]), "r"(b[1]));
}
__device__ __forceinline__ void split_write(__half* hi, __half* lo, size_t gi,
                                            float v0, float v1) {
    __half h0 = __float2half_rn(v0), h1 = __float2half_rn(v1);
    float l0 = v0 - __half2float(h0), l1 = v1 - __half2float(h1);
    *(__half2*)(hi + gi) = __halves2half2(h0, h1);
    *(__half2*)(lo + gi) = __floats2half2_rn(l0, l1);
}

// ---------------- f32 -> f16 weight convert (ternary => exact) ----------------
__global__ void f2h_kernel(const float* __restrict__ a, __half* __restrict__ o, int n) {
    int i = (blockIdx.x * blockDim.x + threadIdx.x) * 4;
    if (i < n) {
        float4 v = *(const float4*)(a + i);
        __half2* p = (__half2*)(o + i);
        p[0] = __floats2half2_rn(v.x, v.y);
        p[1] = __floats2half2_rn(v.z, v.w);
    }
}

// ---------------- LayerNorm: one block per row, split f16 out ----------------
__global__ void ln_kernel(const float* __restrict__ x, const float* __restrict__ g,
                          const float* __restrict__ b,
                          __half* __restrict__ yhi, __half* __restrict__ ylo) {
    __shared__ float red[2][8];
    const int row = blockIdx.x;
    const float* xr = x + (size_t)row * DD;
    float vloc[4];
    float s = 0.f, s2 = 0.f;
#pragma unroll
    for (int i = 0; i < 4; i++) {
        float t = xr[threadIdx.x + 256 * i];
        vloc[i] = t; s += t; s2 += t * t;
    }
#pragma unroll
    for (int o = 16; o; o >>= 1) {
        s  += __shfl_xor_sync(0xffffffffu, s,  o);
        s2 += __shfl_xor_sync(0xffffffffu, s2, o);
    }
    const int w = threadIdx.x >> 5, lane = threadIdx.x & 31;
    if (!lane) { red[0][w] = s; red[1][w] = s2; }
    __syncthreads();
    if (threadIdx.x < 32) {
        s  = (lane < 8) ? red[0][lane] : 0.f;
        s2 = (lane < 8) ? red[1][lane] : 0.f;
#pragma unroll
        for (int o = 4; o; o >>= 1) {
            s  += __shfl_xor_sync(0xffffffffu, s,  o);
            s2 += __shfl_xor_sync(0xffffffffu, s2, o);
        }
        if (!lane) { red[0][0] = s; red[1][0] = s2; }
    }
    __syncthreads();
    s = red[0][0]; s2 = red[1][0];
    const float mu  = s * (1.f / DD);
    const float var = s2 * (1.f / DD) - mu * mu;
    const float inv = rsqrtf(var + 1e-5f);
#pragma unroll
    for (int i = 0; i < 4; i++) {
        int c = threadIdx.x + 256 * i;
        float v = (vloc[i] - mu) * inv * g[c] + b[c];
        __half h = __float2half_rn(v);
        yhi[(size_t)row * DD + c] = h;
        ylo[(size_t)row * DD + c] = __float2half_rn(v - __half2float(h));
    }
}

// ================= split-HMMA GEMM: C = (Ahi+Alo)[M,K] @ W[N,K]^T =================
// CTA 128x128, 8 warps (2m x 4n), warp 64x32, BK=32, cp.async double buffer.
// EPI: 0 none (f32 C), 1 residual add (f32 C), 2 exact GELU (split f16 out)
#define LDS 40     // smem row stride in halfs (80B; ldmatrix conflict-free)
#define TILE_B (128 * LDS * 2)   // 10240 bytes per tile buffer
template <int EPI>
__global__ void __launch_bounds__(256) hgemm(
    const __half* __restrict__ Ahi, const __half* __restrict__ Alo,
    const __half* __restrict__ W,
    const float* __restrict__ R, float* __restrict__ C,
    __half* __restrict__ Ohi, __half* __restrict__ Olo,
    int N, int K)
{
    extern __shared__ __align__(16) char smem_raw[];
    // tiles: Ahi[2], Alo[2], B[2]
    uint32_t sb = smem_u32(smem_raw);
    const uint32_t tAhi[2] = { sb,              sb + TILE_B };
    const uint32_t tAlo[2] = { sb + 2 * TILE_B, sb + 3 * TILE_B };
    const uint32_t tB[2]   = { sb + 4 * TILE_B, sb + 5 * TILE_B };

    const int tid = threadIdx.x, wid = tid >> 5, lane = tid & 31;
    const int wm = wid >> 2, wn = wid & 3;            // warp grid 2x4
    const int m0 = blockIdx.y * 128, n0 = blockIdx.x * 128;

    float acc[4][4][4] = {};
    const int NT = K >> 5;   // BK=32 tiles

    // loader: 512 chunks of 16B per tile; 2 chunks/thread/tile
    auto load_buf = [&](int nb, int kt) {
        const size_t ko = (size_t)(kt << 5);
        const __half* ph = Ahi + (size_t)m0 * K + ko;
        const __half* pl = Alo + (size_t)m0 * K + ko;
        const __half* pw = W   + (size_t)n0 * K + ko;
#pragma unroll
        for (int j = 0; j < 2; j++) {
            const int c = tid + (j << 8);
            const int row = c >> 2, q = c & 3;
            const uint32_t so = (uint32_t)(row * LDS + q * 8) * 2;
            const size_t go = (size_t)row * K + q * 8;
            cp16(tAhi[nb] + so, ph + go);
            cp16(tAlo[nb] + so, pl + go);
            cp16(tB[nb]   + so, pw + go);
        }
        CP_COMMIT();
    };

    load_buf(0, 0);

    // ldmatrix addresses
    const int a_row  = wm * 64 + (lane & 15);
    const int a_koff = (lane >> 4) * 8;
    const int b_row  = wn * 32 + (lane & 7) + ((lane >> 4) & 1) * 8;
    const int b_koff = ((lane >> 3) & 1) * 8;

    for (int kt = 0; kt < NT; kt++) {
        const int buf = kt & 1;
        if (kt + 1 < NT) { load_buf((kt + 1) & 1, kt + 1); CP_WAIT(1); }
        else             { CP_WAIT(0); }
        __syncthreads();

#pragma unroll
        for (int ks = 0; ks < 2; ks++) {
            uint32_t bf[2][4];
#pragma unroll
            for (int nf2 = 0; nf2 < 2; nf2++)
                ldsm4(bf[nf2][0], bf[nf2][1], bf[nf2][2], bf[nf2][3],
                      tB[buf] + (uint32_t)((b_row + nf2 * 16) * LDS + ks * 16 + b_koff) * 2);
#pragma unroll
            for (int pass = 0; pass < 2; pass++) {
                const uint32_t tA = pass ? tAlo[buf] : tAhi[buf];
#pragma unroll
                for (int mf = 0; mf < 4; mf++) {
                    uint32_t a[4];
                    ldsm4(a[0], a[1], a[2], a[3],
                          tA + (uint32_t)((a_row + mf * 16) * LDS + ks * 16 + a_koff) * 2);
#pragma unroll
                    for (int nf = 0; nf < 4; nf++) {
                        uint32_t b[2] = { bf[nf >> 1][(nf & 1) * 2],
                                          bf[nf >> 1][(nf & 1) * 2 + 1] };
                        mma16816(acc[mf][nf], a, b);
                    }
                }
            }
        }
        __syncthreads();
    }

    // ---- epilogue: direct register writes ----
    const int gq = lane >> 2, tq = lane & 3;
#pragma unroll
    for (int mf = 0; mf < 4; mf++) {
#pragma unroll
        for (int nf = 0; nf < 4; nf++) {
            const int row0 = m0 + wm * 64 + mf * 16 + gq;
            const int col  = n0 + wn * 32 + nf * 8 + tq * 2;
#pragma unroll
            for (int hh = 0; hh < 2; hh++) {
                const int row = row0 + hh * 8;
                float v0 = acc[mf][nf][hh * 2 + 0];
                float v1 = acc[mf][nf][hh * 2 + 1];
                const size_t gi = (size_t)row * N + col;
                if (EPI == 1) { v0 += R[gi]; v1 += R[gi + 1]; }
                if (EPI == 2) {
                    v0 = 0.5f * v0 * (1.f + erff(v0 * 0.70710678118654752f));
                    v1 = 0.5f * v1 * (1.f + erff(v1 * 0.70710678118654752f));
                    split_write(Ohi, Olo, gi, v0, v1);
                } else {
                    *(float2*)(C + gi) = make_float2(v0, v1);
                }
            }
        }
    }
}

// ---------------- Causal flash attention (fp32), DH=64, split f16 out ----------------
__global__ void attn_kernel(const float* __restrict__ Q, const float* __restrict__ K,
                            const float* __restrict__ V,
                            __half* __restrict__ Ohi, __half* __restrict__ Olo) {
    extern __shared__ float sm[];
    float* Qs = sm;                 // [64][65]
    float* Ks = sm + 4160;
    float* Vs = sm + 8320;
    float* Ps = sm + 12480;

    const int tid = threadIdx.x;
    const int tx = tid & 15, ty = tid >> 4;
    const int q0 = blockIdx.x * 64;
    const int h  = blockIdx.y;
    const int b  = blockIdx.z;
    const size_t base = ((size_t)b * TT * HH + h) * DHD;
    const int RS = HH * DHD;  // 1024

    for (int i = tid; i < 1024; i += 256) {
        int row = i >> 4, c4 = i & 15;
        float4 qv = *(const float4*)(Q + base + (size_t)(q0 + row) * RS + c4 * 4);
        float* d = &Qs[row * 65 + c4 * 4];
        d[0] = qv.x; d[1] = qv.y; d[2] = qv.z; d[3] = qv.w;
    }

    float acc[4][4] = {};
    float m[4], l[4];
#pragma unroll
    for (int i = 0; i < 4; i++) { m[i] = -1e30f; l[i] = 0.f; }
    __syncthreads();

    for (int k0 = 0; k0 <= q0; k0 += 64) {
        for (int i = tid; i < 1024; i += 256) {
            int row = i >> 4, c4 = i & 15;
            float4 kv = *(const float4*)(K + base + (size_t)(k0 + row) * RS + c4 * 4);
            float4 vv = *(const float4*)(V + base + (size_t)(k0 + row) * RS + c4 * 4);
            float* kd = &Ks[row * 65 + c4 * 4];
            kd[0] = kv.x; kd[1] = kv.y; kd[2] = kv.z; kd[3] = kv.w;
            float* vd = &Vs[row * 65 + c4 * 4];
            vd[0] = vv.x; vd[1] = vv.y; vd[2] = vv.z; vd[3] = vv.w;
        }
        __syncthreads();

        float s[4][4] = {};
#pragma unroll 8
        for (int d = 0; d < 64; d++) {
            float a[4], bb[4];
#pragma unroll
            for (int i = 0; i < 4; i++) a[i]  = Qs[(ty * 4 + i) * 65 + d];
#pragma unroll
            for (int j = 0; j < 4; j++) bb[j] = Ks[(tx * 4 + j) * 65 + d];
#pragma unroll
            for (int i = 0; i < 4; i++)
#pragma unroll
                for (int j = 0; j < 4; j++) s[i][j] += a[i] * bb[j];
        }

        const bool lastt = (k0 == q0);
#pragma unroll
        for (int i = 0; i < 4; i++)
#pragma unroll
            for (int j = 0; j < 4; j++) {
                s[i][j] *= 0.125f;
                if (lastt && (tx * 4 + j > ty * 4 + i)) s[i][j] = -1e30f;
            }

#pragma unroll
        for (int i = 0; i < 4; i++) {
            float mloc = fmaxf(fmaxf(s[i][0], s[i][1]), fmaxf(s[i][2], s[i][3]));
#pragma unroll
            for (int o = 8; o >= 1; o >>= 1)
                mloc = fmaxf(mloc, __shfl_xor_sync(0xffffffffu, mloc, o));
            const float mnew = fmaxf(m[i], mloc);
            const float f = __expf(m[i] - mnew);
            float ls = 0.f;
#pragma unroll
            for (int j = 0; j < 4; j++) { s[i][j] = __expf(s[i][j] - mnew); ls += s[i][j]; }
#pragma unroll
            for (int o = 8; o >= 1; o >>= 1)
                ls += __shfl_xor_sync(0xffffffffu, ls, o);
            l[i] = l[i] * f + ls;
            m[i] = mnew;
#pragma unroll
            for (int j = 0; j < 4; j++) acc[i][j] *= f;
#pragma unroll
            for (int j = 0; j < 4; j++) Ps[(ty * 4 + i) * 65 + tx * 4 + j] = s[i][j];
        }
        __syncwarp();

#pragma unroll 8
        for (int j = 0; j < 64; j++) {
            float p[4], vv[4];
#pragma unroll
            for (int i = 0; i < 4; i++) p[i] = Ps[(ty * 4 + i) * 65 + j];
#pragma unroll
            for (int c = 0; c < 4; c++) vv[c] = Vs[j * 65 + tx * 4 + c];
#pragma unroll
            for (int i = 0; i < 4; i++)
#pragma unroll
                for (int c = 0; c < 4; c++) acc[i][c] += p[i] * vv[c];
        }
        __syncthreads();
    }

#pragma unroll
    for (int i = 0; i < 4; i++) {
        const float linv = 1.f / l[i];
#pragma unroll
        for (int j = 0; j < 4; j += 2) {
            const int row = ty * 4 + i, col = tx * 4 + j;
            const size_t gi = base + (size_t)(q0 + row) * RS + col;
            split_write(Ohi, Olo, gi, acc[i][j] * linv, acc[i][j + 1] * linv);
        }
    }
}

// ---------------- host entry ----------------
extern "C" void kernel_launch(void* const* d_in, const int* in_sizes, int n_in,
                              void* d_out, int out_size) {
    const float* x     = (const float*)d_in[0];
    // d_in[1] = mask (causal; implemented analytically, unused)
    const float* ln1_g = (const float*)d_in[2];
    const float* ln1_b = (const float*)d_in[3];
    const float* ln2_g = (const float*)d_in[4];
    const float* ln2_b = (const float*)d_in[5];
    const float* Wq    = (const float*)d_in[6];
    const float* Wk    = (const float*)d_in[7];
    const float* Wv    = (const float*)d_in[8];
    const float* Wo    = (const float*)d_in[9];
    const float* Wff1  = (const float*)d_in[10];
    const float* Wff2  = (const float*)d_in[11];
    float* out = (float*)d_out;

    __half *hhi, *hlo, *atthi, *attlo, *ffhi, *fflo;
    __half *wq16, *wk16, *wv16, *wo16, *wf1, *wf2;
    float *q, *k, *v;
    cudaGetSymbolAddress((void**)&hhi,   g_hhi);
    cudaGetSymbolAddress((void**)&hlo,   g_hlo);
    cudaGetSymbolAddress((void**)&q,     g_q);
    cudaGetSymbolAddress((void**)&k,     g_k);
    cudaGetSymbolAddress((void**)&v,     g_v);
    cudaGetSymbolAddress((void**)&atthi, g_atthi);
    cudaGetSymbolAddress((void**)&attlo, g_attlo);
    cudaGetSymbolAddress((void**)&ffhi,  g_ffhi);
    cudaGetSymbolAddress((void**)&fflo,  g_fflo);
    cudaGetSymbolAddress((void**)&wq16,  g_wq16);
    cudaGetSymbolAddress((void**)&wk16,  g_wk16);
    cudaGetSymbolAddress((void**)&wv16,  g_wv16);
    cudaGetSymbolAddress((void**)&wo16,  g_wo16);
    cudaGetSymbolAddress((void**)&wf1,   g_wf1_16);
    cudaGetSymbolAddress((void**)&wf2,   g_wf2_16);

    const int SMEM_G = 6 * TILE_B;        // 61440
    cudaFuncSetAttribute(hgemm<0>, cudaFuncAttributeMaxDynamicSharedMemorySize, SMEM_G);
    cudaFuncSetAttribute(hgemm<1>, cudaFuncAttributeMaxDynamicSharedMemorySize, SMEM_G);
    cudaFuncSetAttribute(hgemm<2>, cudaFuncAttributeMaxDynamicSharedMemorySize, SMEM_G);
    const int SMEM_ATTN = 4 * 4160 * 4;   // 66560
    cudaFuncSetAttribute(attn_kernel, cudaFuncAttributeMaxDynamicSharedMemorySize, SMEM_ATTN);

    // weight converts (exact for ternary)
    const int DD2 = DD * DD, DF = DD * FFD;
    f2h_kernel<<<DD2 / 1024, 256>>>(Wq,   wq16, DD2);
    f2h_kernel<<<DD2 / 1024, 256>>>(Wk,   wk16, DD2);
    f2h_kernel<<<DD2 / 1024, 256>>>(Wv,   wv16, DD2);
    f2h_kernel<<<DD2 / 1024, 256>>>(Wo,   wo16, DD2);
    f2h_kernel<<<DF  / 1024, 256>>>(Wff1, wf1,  DF);
    f2h_kernel<<<DF  / 1024, 256>>>(Wff2, wf2,  DF);

    // h = LN1(x)  (split f16)
    ln_kernel<<<ROWS, 256>>>(x, ln1_g, ln1_b, hhi, hlo);

    // Q,K,V projections (split HMMA), fp32 out
    dim3 gP(DD / 128, ROWS / 128);      // (8, 32)
    hgemm<0><<<gP, 256, SMEM_G>>>(hhi, hlo, wq16, nullptr, q, nullptr, nullptr, DD, DD);
    hgemm<0><<<gP, 256, SMEM_G>>>(hhi, hlo, wk16, nullptr, k, nullptr, nullptr, DD, DD);
    hgemm<0><<<gP, 256, SMEM_G>>>(hhi, hlo, wv16, nullptr, v, nullptr, nullptr, DD, DD);

    // causal attention -> split f16
    attn_kernel<<<dim3(TT / 64, HH, BB), 256, SMEM_ATTN>>>(q, k, v, atthi, attlo);

    // out = x + att @ Wo^T
    hgemm<1><<<gP, 256, SMEM_G>>>(atthi, attlo, wo16, x, out, nullptr, nullptr, DD, DD);

    // h = LN2(out)
    ln_kernel<<<ROWS, 256>>>(out, ln2_g, ln2_b, hhi, hlo);

    // ff = gelu(h @ Wff1^T)  (split f16)
    hgemm<2><<<dim3(FFD / 128, ROWS / 128), 256, SMEM_G>>>(hhi, hlo, wf1, nullptr, nullptr,
                                                           ffhi, fflo, FFD, DD);

    // out = out + ff @ Wff2^T
    hgemm<1><<<gP, 256, SMEM_G>>>(ffhi, fflo, wf2, out, out, nullptr, nullptr, DD, FFD);
}